// round 1
// baseline (speedup 1.0000x reference)
#include <cuda_runtime.h>
#include <math.h>

// ---------------- problem constants ----------------
#define Bn   64
#define Kn   64
#define Np   32768
#define Dn   2048
#define NCn  2048
#define NH   512
#define CDn  4096      // 2*Dn
#define RWS  4096      // Bn*Kn

// ---------------- device scratch (no allocations allowed) ----------------
__device__ int   g_counts[NCn];
__device__ int   g_offsets[NCn + 1];
__device__ int   g_cursor[NCn];
__device__ int   g_bucket[Np];
__device__ float g_clu[(size_t)NCn * Dn];        // 16 MB cluster means
__device__ float g_cat[(size_t)RWS * CDn];       // 64 MB [x | agg] concat buffer
__device__ float g_adj[RWS * Kn];                // 1 MB adjacency
__device__ float g_rinv[RWS];
__device__ float g_q[Bn * Dn];                   // normalized query rows
__device__ float g_h[(size_t)RWS * NH];          // 8 MB
__device__ float g_h1[(size_t)RWS * NH];         // 8 MB

// ---------------- cluster mean via deterministic bucketing ----------------
__global__ void zero_counts_k() {
    int i = blockIdx.x * blockDim.x + threadIdx.x;
    if (i < NCn) g_counts[i] = 0;
}

__global__ void count_k(const int* __restrict__ labels) {
    int n = blockIdx.x * blockDim.x + threadIdx.x;
    if (n < Np) atomicAdd(&g_counts[labels[n]], 1);
}

// single block, 1024 threads: inclusive Hillis-Steele over 2048 counters
__global__ void scan_k() {
    __shared__ int s[NCn];
    int t = threadIdx.x;
    s[t]        = g_counts[t];
    s[t + 1024] = g_counts[t + 1024];
    __syncthreads();
    for (int off = 1; off < NCn; off <<= 1) {
        int v0 = (t >= off) ? s[t - off] : 0;
        int v1 = s[t + 1024 - off];
        __syncthreads();
        s[t]        += v0;
        s[t + 1024] += v1;
        __syncthreads();
    }
    g_offsets[t]        = (t == 0) ? 0 : s[t - 1];
    g_offsets[t + 1024] = s[t + 1023];
    if (t == 0) g_offsets[NCn] = s[NCn - 1];
    __syncthreads();
    g_cursor[t]        = g_offsets[t];
    g_cursor[t + 1024] = g_offsets[t + 1024];
}

__global__ void scatter_k(const int* __restrict__ labels) {
    int n = blockIdx.x * blockDim.x + threadIdx.x;
    if (n < Np) {
        int pos = atomicAdd(&g_cursor[labels[n]], 1);
        g_bucket[pos] = n;
    }
}

// sort each bucket ascending -> deterministic summation order
__global__ void sortbucket_k() {
    int c = blockIdx.x * blockDim.x + threadIdx.x;
    if (c >= NCn) return;
    int s = g_offsets[c], e = g_offsets[c + 1];
    for (int i = s + 1; i < e; i++) {
        int v = g_bucket[i];
        int j = i - 1;
        while (j >= s && g_bucket[j] > v) { g_bucket[j + 1] = g_bucket[j]; j--; }
        g_bucket[j + 1] = v;
    }
}

// grid (Dn/256, NCn), 256 threads
__global__ void clumean_k(const float* __restrict__ features) {
    int c = blockIdx.y;
    int d = blockIdx.x * 256 + threadIdx.x;
    int s = g_offsets[c], e = g_offsets[c + 1];
    float sum = 0.f;
    for (int m = s; m < e; ++m)
        sum += features[(size_t)g_bucket[m] * Dn + d];
    g_clu[(size_t)c * Dn + d] = sum / fmaxf((float)(e - s), 1.f);
}

// ---------------- per-sample graph construction ----------------
// cf rows -> g_cat[:, 0:Dn]
__global__ void build_cf_k(const int* __restrict__ indexes,
                           const float* __restrict__ features,
                           const int* __restrict__ labels,
                           const int* __restrict__ nbr) {
    int r = blockIdx.x, t = threadIdx.x;
    int b = r >> 6, k = r & 63;
    const float* src;
    if (k == 0) src = features + (size_t)indexes[b] * Dn;
    else        src = g_clu + (size_t)labels[nbr[r]] * Dn;
    const float4* s4 = (const float4*)src;
    float4* d4 = (float4*)(g_cat + (size_t)r * CDn);
    #pragma unroll
    for (int i = t; i < Dn / 4; i += 256) d4[i] = s4[i];
}

// A = cf cf^T / 5   (one block per sample, 64x64 output, smem tiles over D)
__global__ void __launch_bounds__(256) a_k() {
    __shared__ float tile[64][65];
    int b = blockIdx.x, t = threadIdx.x;
    int tx = t & 15, ty = t >> 4;
    float acc[4][4] = {};
    for (int c0 = 0; c0 < Dn; c0 += 64) {
        #pragma unroll
        for (int it = 0; it < 16; ++it) {
            int idx = t + 256 * it;
            int row = idx >> 6, col = idx & 63;
            tile[row][col] = g_cat[(size_t)(b * 64 + row) * CDn + c0 + col];
        }
        __syncthreads();
        #pragma unroll 8
        for (int dc = 0; dc < 64; dc++) {
            float a0 = tile[ty * 4 + 0][dc], a1 = tile[ty * 4 + 1][dc];
            float a2 = tile[ty * 4 + 2][dc], a3 = tile[ty * 4 + 3][dc];
            float b0 = tile[tx * 4 + 0][dc], b1 = tile[tx * 4 + 1][dc];
            float b2 = tile[tx * 4 + 2][dc], b3 = tile[tx * 4 + 3][dc];
            acc[0][0] += a0 * b0; acc[0][1] += a0 * b1; acc[0][2] += a0 * b2; acc[0][3] += a0 * b3;
            acc[1][0] += a1 * b0; acc[1][1] += a1 * b1; acc[1][2] += a1 * b2; acc[1][3] += a1 * b3;
            acc[2][0] += a2 * b0; acc[2][1] += a2 * b1; acc[2][2] += a2 * b2; acc[2][3] += a2 * b3;
            acc[3][0] += a3 * b0; acc[3][1] += a3 * b1; acc[3][2] += a3 * b2; acc[3][3] += a3 * b3;
        }
        __syncthreads();
    }
    #pragma unroll
    for (int ii = 0; ii < 4; ii++)
        #pragma unroll
        for (int jj = 0; jj < 4; jj++)
            g_adj[(b * 64 + ty * 4 + ii) * 64 + tx * 4 + jj] = acc[ii][jj] / 5.0f;
}

// keep-mask (first occurrence of cluster label) + mutual top-5 mask
__global__ void mask_k(const int* __restrict__ labels, const int* __restrict__ nbr) {
    __shared__ float As[64][65];
    __shared__ unsigned long long rm[64];
    __shared__ int lab[64];
    __shared__ int keep[64];
    int b = blockIdx.x, t = threadIdx.x;   // 64 threads
    lab[t] = labels[nbr[b * 64 + t]];
    for (int it = 0; it < 64; it++)
        As[it][t] = g_adj[(b * 64 + it) * 64 + t];
    __syncthreads();
    int dup = 0;
    for (int j = 0; j < t; j++) dup |= (lab[j] == lab[t]);
    keep[t] = !dup;
    // stable top-5 of row t: strict > with ascending scan => lower index wins ties
    unsigned long long sel = 0ULL;
    for (int r = 0; r < 5; r++) {
        float best = -3.4e38f; int bi = 0;
        for (int j = 0; j < 64; j++) {
            float v = As[t][j];
            if (!((sel >> j) & 1ULL) && v > best) { best = v; bi = j; }
        }
        sel |= 1ULL << bi;
    }
    rm[t] = sel;
    __syncthreads();
    bool kt = keep[t];
    for (int j = 0; j < 64; j++) {
        bool mm = kt && keep[j] && ((rm[t] >> j) & 1ULL) && ((rm[j] >> t) & 1ULL);
        g_adj[(b * 64 + t) * 64 + j] = mm ? As[t][j] : 0.f;
    }
}

// per-row inverse L2 norm of raw cf
__global__ void norm_k() {
    int r = blockIdx.x, t = threadIdx.x;
    const float4* p = (const float4*)(g_cat + (size_t)r * CDn);
    float s = 0.f;
    #pragma unroll
    for (int i = t; i < Dn / 4; i += 256) {
        float4 v = p[i];
        s += v.x * v.x + v.y * v.y + v.z * v.z + v.w * v.w;
    }
    __shared__ float red[8];
    #pragma unroll
    for (int o = 16; o; o >>= 1) s += __shfl_xor_sync(0xffffffffu, s, o);
    if ((t & 31) == 0) red[t >> 5] = s;
    __syncthreads();
    if (t < 8) {
        float v = red[t];
        #pragma unroll
        for (int o = 4; o; o >>= 1) v += __shfl_xor_sync(0xffu, v, o);
        if (t == 0) g_rinv[r] = 1.f / sqrtf(v);
    }
}

// save normalized query row (avoids in-place race on row 0)
__global__ void q_k() {
    int b = blockIdx.x, t = threadIdx.x;
    float rv = g_rinv[b * 64];
    for (int d = t; d < Dn; d += 256)
        g_q[b * Dn + d] = g_cat[(size_t)(b * 64) * CDn + d] * rv;
}

// x = cf/||cf|| - q  (row 0 -> exact 0 by identical-op cancellation)
__global__ void center_k() {
    int r = blockIdx.x, t = threadIdx.x;
    int b = r >> 6;
    float rv = g_rinv[r];
    for (int d = t; d < Dn; d += 256) {
        size_t i = (size_t)r * CDn + d;
        g_cat[i] = g_cat[i] * rv - g_q[b * Dn + d];
    }
}

// agg = adj @ x  -> g_cat[:, Dn:2Dn];  grid (Dn/64, Bn)
__global__ void __launch_bounds__(256) agg_k() {
    __shared__ float adjs[64][65];
    __shared__ float xs[64][65];
    int d0 = blockIdx.x * 64, b = blockIdx.y;
    int t = threadIdx.x, tx = t & 15, ty = t >> 4;
    #pragma unroll
    for (int it = 0; it < 16; ++it) {
        int idx = t + 256 * it;
        int row = idx >> 6, col = idx & 63;
        adjs[row][col] = g_adj[(b * 64 + row) * 64 + col];
        xs[row][col]   = g_cat[(size_t)(b * 64 + row) * CDn + d0 + col];
    }
    __syncthreads();
    float acc[4][4] = {};
    #pragma unroll 8
    for (int j = 0; j < 64; j++) {
        float a0 = adjs[ty * 4 + 0][j], a1 = adjs[ty * 4 + 1][j];
        float a2 = adjs[ty * 4 + 2][j], a3 = adjs[ty * 4 + 3][j];
        float x0 = xs[j][tx * 4 + 0], x1 = xs[j][tx * 4 + 1];
        float x2 = xs[j][tx * 4 + 2], x3 = xs[j][tx * 4 + 3];
        acc[0][0] += a0 * x0; acc[0][1] += a0 * x1; acc[0][2] += a0 * x2; acc[0][3] += a0 * x3;
        acc[1][0] += a1 * x0; acc[1][1] += a1 * x1; acc[1][2] += a1 * x2; acc[1][3] += a1 * x3;
        acc[2][0] += a2 * x0; acc[2][1] += a2 * x1; acc[2][2] += a2 * x2; acc[2][3] += a2 * x3;
        acc[3][0] += a3 * x0; acc[3][1] += a3 * x1; acc[3][2] += a3 * x2; acc[3][3] += a3 * x3;
    }
    #pragma unroll
    for (int ii = 0; ii < 4; ii++)
        #pragma unroll
        for (int cc = 0; cc < 4; cc++)
            g_cat[(size_t)(b * 64 + ty * 4 + ii) * CDn + Dn + d0 + tx * 4 + cc] = acc[ii][cc];
}

// ---------------- fused GEMMs ----------------
// MODE 0: h  = relu(cat @ conv_w + conv_b),  A=g_cat [4096x4096], C=g_h
// MODE 1: h1 = prelu(h @ w1 + b1, pa),       A=g_h  [4096x512],   C=g_h1
// BM=128, BN=64, BK=16, 256 threads, 8x4 per thread
template <int MODE>
__global__ void __launch_bounds__(256) gemm_k(const float* __restrict__ W,
                                              const float* __restrict__ bias,
                                              const float* __restrict__ pa) {
    constexpr int Kd = (MODE == 0) ? CDn : NH;
    const float* A = (MODE == 0) ? g_cat : g_h;
    float* C = (MODE == 0) ? g_h : g_h1;
    __shared__ float As[16][132];   // transposed A tile, padded
    __shared__ float Bs[16][64];
    int tid = threadIdx.x;
    int tx = tid & 15, ty = tid >> 4;
    int m0 = blockIdx.y * 128, n0 = blockIdx.x * 64;
    int ar = tid >> 2, ac = (tid & 3) * 4;
    int br = tid >> 4, bc = (tid & 15) * 4;
    const float* Ap0 = A + (size_t)(m0 + ar) * Kd;
    const float* Ap1 = A + (size_t)(m0 + ar + 64) * Kd;
    const float* Wp  = W + (size_t)br * NH + n0 + bc;
    float acc[8][4] = {};
    for (int k0 = 0; k0 < Kd; k0 += 16) {
        float4 a0 = *(const float4*)(Ap0 + k0 + ac);
        float4 a1 = *(const float4*)(Ap1 + k0 + ac);
        float4 bv = *(const float4*)(Wp + (size_t)k0 * NH);
        __syncthreads();
        As[ac + 0][ar] = a0.x; As[ac + 1][ar] = a0.y; As[ac + 2][ar] = a0.z; As[ac + 3][ar] = a0.w;
        As[ac + 0][ar + 64] = a1.x; As[ac + 1][ar + 64] = a1.y;
        As[ac + 2][ar + 64] = a1.z; As[ac + 3][ar + 64] = a1.w;
        *(float4*)&Bs[br][bc] = bv;
        __syncthreads();
        #pragma unroll
        for (int kk = 0; kk < 16; kk++) {
            float a[8], bb[4];
            *(float4*)&a[0] = *(const float4*)&As[kk][ty * 8];
            *(float4*)&a[4] = *(const float4*)&As[kk][ty * 8 + 4];
            *(float4*)&bb[0] = *(const float4*)&Bs[kk][tx * 4];
            #pragma unroll
            for (int i = 0; i < 8; i++)
                #pragma unroll
                for (int j = 0; j < 4; j++)
                    acc[i][j] += a[i] * bb[j];
        }
    }
    float4 bias4 = *(const float4*)(bias + n0 + tx * 4);
    float4 pa4 = make_float4(0.f, 0.f, 0.f, 0.f);
    if (MODE == 1) pa4 = *(const float4*)(pa + n0 + tx * 4);
    #pragma unroll
    for (int i = 0; i < 8; i++) {
        float4 v;
        v.x = acc[i][0] + bias4.x;
        v.y = acc[i][1] + bias4.y;
        v.z = acc[i][2] + bias4.z;
        v.w = acc[i][3] + bias4.w;
        if (MODE == 0) {
            v.x = fmaxf(v.x, 0.f); v.y = fmaxf(v.y, 0.f);
            v.z = fmaxf(v.z, 0.f); v.w = fmaxf(v.w, 0.f);
        } else {
            v.x = (v.x > 0.f) ? v.x : pa4.x * v.x;
            v.y = (v.y > 0.f) ? v.y : pa4.y * v.y;
            v.z = (v.z > 0.f) ? v.z : pa4.z * v.z;
            v.w = (v.w > 0.f) ? v.w : pa4.w * v.w;
        }
        *(float4*)&C[(size_t)(m0 + ty * 8 + i) * NH + n0 + tx * 4] = v;
    }
}

// logits = h1 @ w2 + b2 ; softmax over 2
__global__ void fc2_softmax_k(const float* __restrict__ w2,
                              const float* __restrict__ b2,
                              float* __restrict__ out) {
    int gw = (blockIdx.x * blockDim.x + threadIdx.x) >> 5;
    int lane = threadIdx.x & 31;
    int nw = (gridDim.x * blockDim.x) >> 5;
    for (int r = gw; r < RWS; r += nw) {
        const float* h = g_h1 + (size_t)r * NH;
        float s0 = 0.f, s1 = 0.f;
        #pragma unroll
        for (int i = lane; i < NH; i += 32) {
            float v = h[i];
            s0 += v * w2[2 * i];
            s1 += v * w2[2 * i + 1];
        }
        #pragma unroll
        for (int o = 16; o; o >>= 1) {
            s0 += __shfl_xor_sync(0xffffffffu, s0, o);
            s1 += __shfl_xor_sync(0xffffffffu, s1, o);
        }
        if (lane == 0) {
            float l0 = s0 + b2[0], l1 = s1 + b2[1];
            float m = fmaxf(l0, l1);
            float e0 = expf(l0 - m), e1 = expf(l1 - m);
            float inv = 1.f / (e0 + e1);
            out[2 * r] = e0 * inv;
            out[2 * r + 1] = e1 * inv;
        }
    }
}

// ---------------- launch ----------------
extern "C" void kernel_launch(void* const* d_in, const int* in_sizes, int n_in,
                              void* d_out, int out_size) {
    const int*   indexes  = (const int*)d_in[0];
    const float* features = (const float*)d_in[1];
    const int*   labels   = (const int*)d_in[2];
    const int*   nbr      = (const int*)d_in[3];
    const float* conv_w   = (const float*)d_in[4];
    const float* conv_b   = (const float*)d_in[5];
    const float* w1       = (const float*)d_in[6];
    const float* b1       = (const float*)d_in[7];
    const float* pa       = (const float*)d_in[8];
    const float* w2       = (const float*)d_in[9];
    const float* b2       = (const float*)d_in[10];
    float* out = (float*)d_out;

    zero_counts_k<<<NCn / 256, 256>>>();
    count_k<<<Np / 256, 256>>>(labels);
    scan_k<<<1, 1024>>>();
    scatter_k<<<Np / 256, 256>>>(labels);
    sortbucket_k<<<(NCn + 255) / 256, 256>>>();
    clumean_k<<<dim3(Dn / 256, NCn), 256>>>(features);
    build_cf_k<<<RWS, 256>>>(indexes, features, labels, nbr);
    a_k<<<Bn, 256>>>();
    mask_k<<<Bn, 64>>>(labels, nbr);
    norm_k<<<RWS, 256>>>();
    q_k<<<Bn, 256>>>();
    center_k<<<RWS, 256>>>();
    agg_k<<<dim3(Dn / 64, Bn), 256>>>();
    gemm_k<0><<<dim3(NH / 64, RWS / 128), 256>>>(conv_w, conv_b, nullptr);
    gemm_k<1><<<dim3(NH / 64, RWS / 128), 256>>>(w1, b1, pa);
    fc2_softmax_k<<<64, 256>>>(w2, b2, out);
}

// round 3
// speedup vs baseline: 2.1378x; 2.1378x over previous
#include <cuda_runtime.h>
#include <cuda_bf16.h>
#include <stdint.h>
#include <cstdint>
#include <math.h>

// ---------------- problem constants ----------------
#define Bn   64
#define Kn   64
#define Np   32768
#define Dn   2048
#define NCn  2048
#define NH   512
#define CDn  4096      // 2*Dn
#define RWS  4096      // Bn*Kn

// ---------------- device scratch ----------------
__device__ int   g_counts[NCn];
__device__ int   g_offsets[NCn + 1];
__device__ int   g_cursor[NCn];
__device__ int   g_bucket[Np];
__device__ float g_clu[(size_t)NCn * Dn];          // 16 MB cluster means
__device__ float g_x[(size_t)RWS * Dn];            // 32 MB fp32 cf -> x
__device__ __nv_bfloat16 g_catb[(size_t)RWS * CDn];// 32 MB bf16 [x | agg]
__device__ float g_adj[RWS * Kn];                  // 1 MB
__device__ float g_apart[8 * Bn * Kn * Kn];        // 8 MB split-K partials
__device__ float g_rinv[RWS];
__device__ float g_q[Bn * Dn];
__device__ __nv_bfloat16 g_hb[(size_t)RWS * NH];   // 4 MB
__device__ float g_h1[(size_t)RWS * NH];           // 8 MB
__device__ __nv_bfloat16 g_wb[(size_t)CDn * NH];   // 4 MB
__device__ __nv_bfloat16 g_w1b[NH * NH];           // 0.5 MB

// ---------------- cluster mean via deterministic bucketing ----------------
__global__ void zero_counts_k() {
    int i = blockIdx.x * blockDim.x + threadIdx.x;
    if (i < NCn) g_counts[i] = 0;
}

__global__ void count_k(const int* __restrict__ labels) {
    int n = blockIdx.x * blockDim.x + threadIdx.x;
    if (n < Np) atomicAdd(&g_counts[labels[n]], 1);
}

__global__ void scan_k() {
    __shared__ int s[NCn];
    int t = threadIdx.x;
    s[t]        = g_counts[t];
    s[t + 1024] = g_counts[t + 1024];
    __syncthreads();
    for (int off = 1; off < NCn; off <<= 1) {
        int v0 = (t >= off) ? s[t - off] : 0;
        int v1 = s[t + 1024 - off];
        __syncthreads();
        s[t]        += v0;
        s[t + 1024] += v1;
        __syncthreads();
    }
    g_offsets[t]        = (t == 0) ? 0 : s[t - 1];
    g_offsets[t + 1024] = s[t + 1023];
    if (t == 0) g_offsets[NCn] = s[NCn - 1];
    __syncthreads();
    g_cursor[t]        = g_offsets[t];
    g_cursor[t + 1024] = g_offsets[t + 1024];
}

__global__ void scatter_k(const int* __restrict__ labels) {
    int n = blockIdx.x * blockDim.x + threadIdx.x;
    if (n < Np) {
        int pos = atomicAdd(&g_cursor[labels[n]], 1);
        g_bucket[pos] = n;
    }
}

__global__ void sortbucket_k() {
    int c = blockIdx.x * blockDim.x + threadIdx.x;
    if (c >= NCn) return;
    int s = g_offsets[c], e = g_offsets[c + 1];
    for (int i = s + 1; i < e; i++) {
        int v = g_bucket[i];
        int j = i - 1;
        while (j >= s && g_bucket[j] > v) { g_bucket[j + 1] = g_bucket[j]; j--; }
        g_bucket[j + 1] = v;
    }
}

__global__ void clumean_k(const float* __restrict__ features) {
    int c = blockIdx.y;
    int d = blockIdx.x * 256 + threadIdx.x;
    int s = g_offsets[c], e = g_offsets[c + 1];
    float sum = 0.f;
    for (int m = s; m < e; ++m)
        sum += features[(size_t)g_bucket[m] * Dn + d];
    g_clu[(size_t)c * Dn + d] = sum / fmaxf((float)(e - s), 1.f);
}

// ---------------- weight conversion to bf16 ----------------
__global__ void convw_k(const float* __restrict__ w, const float* __restrict__ w1) {
    int i = blockIdx.x * 256 + threadIdx.x;
    if (i < CDn * NH) g_wb[i] = __float2bfloat16(w[i]);
    if (i < NH * NH)  g_w1b[i] = __float2bfloat16(w1[i]);
}

// ---------------- per-sample graph construction ----------------
__global__ void build_cf_k(const int* __restrict__ indexes,
                           const float* __restrict__ features,
                           const int* __restrict__ labels,
                           const int* __restrict__ nbr) {
    int r = blockIdx.x, t = threadIdx.x;
    int b = r >> 6, k = r & 63;
    const float* src;
    if (k == 0) src = features + (size_t)indexes[b] * Dn;
    else        src = g_clu + (size_t)labels[nbr[r]] * Dn;
    const float4* s4 = (const float4*)src;
    float4* d4 = (float4*)(g_x + (size_t)r * Dn);
    #pragma unroll
    for (int i = t; i < Dn / 4; i += 256) d4[i] = s4[i];
}

// A partial = cf cf^T over a K chunk of 256; grid (8, Bn)
__global__ void __launch_bounds__(256) a_k() {
    __shared__ float tile[64][65];
    int chunk = blockIdx.x, b = blockIdx.y, t = threadIdx.x;
    int tx = t & 15, ty = t >> 4;
    float acc[4][4] = {};
    for (int c0 = chunk * 256; c0 < chunk * 256 + 256; c0 += 64) {
        #pragma unroll
        for (int it = 0; it < 16; ++it) {
            int idx = t + 256 * it;
            int row = idx >> 6, col = idx & 63;
            tile[row][col] = g_x[(size_t)(b * 64 + row) * Dn + c0 + col];
        }
        __syncthreads();
        #pragma unroll 8
        for (int dc = 0; dc < 64; dc++) {
            float a0 = tile[ty * 4 + 0][dc], a1 = tile[ty * 4 + 1][dc];
            float a2 = tile[ty * 4 + 2][dc], a3 = tile[ty * 4 + 3][dc];
            float b0 = tile[tx * 4 + 0][dc], b1 = tile[tx * 4 + 1][dc];
            float b2 = tile[tx * 4 + 2][dc], b3 = tile[tx * 4 + 3][dc];
            acc[0][0] += a0 * b0; acc[0][1] += a0 * b1; acc[0][2] += a0 * b2; acc[0][3] += a0 * b3;
            acc[1][0] += a1 * b0; acc[1][1] += a1 * b1; acc[1][2] += a1 * b2; acc[1][3] += a1 * b3;
            acc[2][0] += a2 * b0; acc[2][1] += a2 * b1; acc[2][2] += a2 * b2; acc[2][3] += a2 * b3;
            acc[3][0] += a3 * b0; acc[3][1] += a3 * b1; acc[3][2] += a3 * b2; acc[3][3] += a3 * b3;
        }
        __syncthreads();
    }
    float* dst = g_apart + (size_t)(chunk * Bn + b) * 4096;
    #pragma unroll
    for (int ii = 0; ii < 4; ii++)
        #pragma unroll
        for (int jj = 0; jj < 4; jj++)
            dst[(ty * 4 + ii) * 64 + tx * 4 + jj] = acc[ii][jj];
}

// deterministic fixed-order reduce of the 8 partials, fold /5
__global__ void a_reduce_k() {
    int i = blockIdx.x * 256 + threadIdx.x;     // Bn*4096 = 262144
    int b = i >> 12, loc = i & 4095;
    float s = 0.f;
    #pragma unroll
    for (int c = 0; c < 8; c++) s += g_apart[(size_t)(c * Bn + b) * 4096 + loc];
    g_adj[i] = s * 0.2f;
}

// keep-mask + mutual top-5 mask (fp32, stable tie-break = lower index)
__global__ void mask_k(const int* __restrict__ labels, const int* __restrict__ nbr) {
    __shared__ float As[64][65];
    __shared__ unsigned long long rm[64];
    __shared__ int lab[64];
    __shared__ int keep[64];
    int b = blockIdx.x, t = threadIdx.x;   // 64 threads
    lab[t] = labels[nbr[b * 64 + t]];
    for (int it = 0; it < 64; it++)
        As[it][t] = g_adj[(b * 64 + it) * 64 + t];
    __syncthreads();
    int dup = 0;
    for (int j = 0; j < t; j++) dup |= (lab[j] == lab[t]);
    keep[t] = !dup;
    unsigned long long sel = 0ULL;
    for (int r = 0; r < 5; r++) {
        float best = -3.4e38f; int bi = 0;
        for (int j = 0; j < 64; j++) {
            float v = As[t][j];
            if (!((sel >> j) & 1ULL) && v > best) { best = v; bi = j; }
        }
        sel |= 1ULL << bi;
    }
    rm[t] = sel;
    __syncthreads();
    bool kt = keep[t];
    for (int j = 0; j < 64; j++) {
        bool mm = kt && keep[j] && ((rm[t] >> j) & 1ULL) && ((rm[j] >> t) & 1ULL);
        g_adj[(b * 64 + t) * 64 + j] = mm ? As[t][j] : 0.f;
    }
}

__global__ void norm_k() {
    int r = blockIdx.x, t = threadIdx.x;
    const float4* p = (const float4*)(g_x + (size_t)r * Dn);
    float s = 0.f;
    #pragma unroll
    for (int i = t; i < Dn / 4; i += 256) {
        float4 v = p[i];
        s += v.x * v.x + v.y * v.y + v.z * v.z + v.w * v.w;
    }
    __shared__ float red[8];
    #pragma unroll
    for (int o = 16; o; o >>= 1) s += __shfl_xor_sync(0xffffffffu, s, o);
    if ((t & 31) == 0) red[t >> 5] = s;
    __syncthreads();
    if (t < 8) {
        float v = red[t];
        #pragma unroll
        for (int o = 4; o; o >>= 1) v += __shfl_xor_sync(0xffu, v, o);
        if (t == 0) g_rinv[r] = 1.f / sqrtf(v);
    }
}

__global__ void q_k() {
    int b = blockIdx.x, t = threadIdx.x;
    float rv = g_rinv[b * 64];
    for (int d = t; d < Dn; d += 256)
        g_q[b * Dn + d] = g_x[(size_t)(b * 64) * Dn + d] * rv;
}

// x = cf/||cf|| - q ; write fp32 (for agg) + bf16 (for GEMM)
__global__ void center_k() {
    int r = blockIdx.x, t = threadIdx.x;
    int b = r >> 6;
    float rv = g_rinv[r];
    for (int d = t; d < Dn; d += 256) {
        size_t i = (size_t)r * Dn + d;
        float v = g_x[i] * rv - g_q[b * Dn + d];
        g_x[i] = v;
        g_catb[(size_t)r * CDn + d] = __float2bfloat16(v);
    }
}

// agg = adj @ x -> bf16 g_catb[:, Dn:2Dn]; grid (Dn/64, Bn)
__global__ void __launch_bounds__(256) agg_k() {
    __shared__ float adjs[64][65];
    __shared__ float xs[64][65];
    int d0 = blockIdx.x * 64, b = blockIdx.y;
    int t = threadIdx.x, tx = t & 15, ty = t >> 4;
    #pragma unroll
    for (int it = 0; it < 16; ++it) {
        int idx = t + 256 * it;
        int row = idx >> 6, col = idx & 63;
        adjs[row][col] = g_adj[(b * 64 + row) * 64 + col];
        xs[row][col]   = g_x[(size_t)(b * 64 + row) * Dn + d0 + col];
    }
    __syncthreads();
    float acc[4][4] = {};
    #pragma unroll 8
    for (int j = 0; j < 64; j++) {
        float a0 = adjs[ty * 4 + 0][j], a1 = adjs[ty * 4 + 1][j];
        float a2 = adjs[ty * 4 + 2][j], a3 = adjs[ty * 4 + 3][j];
        float x0 = xs[j][tx * 4 + 0], x1 = xs[j][tx * 4 + 1];
        float x2 = xs[j][tx * 4 + 2], x3 = xs[j][tx * 4 + 3];
        acc[0][0] += a0 * x0; acc[0][1] += a0 * x1; acc[0][2] += a0 * x2; acc[0][3] += a0 * x3;
        acc[1][0] += a1 * x0; acc[1][1] += a1 * x1; acc[1][2] += a1 * x2; acc[1][3] += a1 * x3;
        acc[2][0] += a2 * x0; acc[2][1] += a2 * x1; acc[2][2] += a2 * x2; acc[2][3] += a2 * x3;
        acc[3][0] += a3 * x0; acc[3][1] += a3 * x1; acc[3][2] += a3 * x2; acc[3][3] += a3 * x3;
    }
    #pragma unroll
    for (int ii = 0; ii < 4; ii++) {
        size_t base = (size_t)(b * 64 + ty * 4 + ii) * CDn + Dn + d0 + tx * 4;
        *(__nv_bfloat162*)&g_catb[base]     = __floats2bfloat162_rn(acc[ii][0], acc[ii][1]);
        *(__nv_bfloat162*)&g_catb[base + 2] = __floats2bfloat162_rn(acc[ii][2], acc[ii][3]);
    }
}

// ---------------- bf16 tensor-core GEMMs ----------------
__device__ __forceinline__ void ldsm4(unsigned* r, unsigned a) {
    asm volatile("ldmatrix.sync.aligned.m8n8.x4.shared.b16 {%0,%1,%2,%3}, [%4];"
        : "=r"(r[0]), "=r"(r[1]), "=r"(r[2]), "=r"(r[3]) : "r"(a));
}
__device__ __forceinline__ void ldsm4t(unsigned* r, unsigned a) {
    asm volatile("ldmatrix.sync.aligned.m8n8.x4.trans.shared.b16 {%0,%1,%2,%3}, [%4];"
        : "=r"(r[0]), "=r"(r[1]), "=r"(r[2]), "=r"(r[3]) : "r"(a));
}
__device__ __forceinline__ void mma16816(float* c, const unsigned* a, unsigned b0, unsigned b1) {
    asm volatile("mma.sync.aligned.m16n8k16.row.col.f32.bf16.bf16.f32 "
        "{%0,%1,%2,%3}, {%4,%5,%6,%7}, {%8,%9}, {%0,%1,%2,%3};"
        : "+f"(c[0]), "+f"(c[1]), "+f"(c[2]), "+f"(c[3])
        : "r"(a[0]), "r"(a[1]), "r"(a[2]), "r"(a[3]), "r"(b0), "r"(b1));
}

// BM=128, BN=128, BK=64; 256 threads = 8 warps (4 M x 2 N), warp tile 32x64.
// MODE 0: h = relu(catb @ wb + conv_b)      -> g_hb (bf16), K=4096
// MODE 1: h1 = prelu(hb @ w1b + b1, pa)     -> g_h1 (fp32), K=512
template <int MODE>
__global__ void __launch_bounds__(256) mgemm_k(const float* __restrict__ bias,
                                               const float* __restrict__ pa) {
    constexpr int Kd = (MODE == 0) ? CDn : NH;
    const __nv_bfloat16* A = (MODE == 0) ? g_catb : g_hb;
    const __nv_bfloat16* W = (MODE == 0) ? g_wb : g_w1b;
    __shared__ __nv_bfloat16 As[128 * 64];
    __shared__ __nv_bfloat16 Bs[64 * 128];
    int tid = threadIdx.x;
    int lane = tid & 31, warp = tid >> 5;
    int wm = (warp & 3) * 32, wn = (warp >> 2) * 64;
    int m0 = blockIdx.y * 128, n0 = blockIdx.x * 128;
    unsigned as_u = (unsigned)__cvta_generic_to_shared(As);
    unsigned bs_u = (unsigned)__cvta_generic_to_shared(Bs);

    // gmem load mapping
    int ar = tid >> 1, ac0 = (tid & 1) * 4;       // A: 128 rows x 8 chunks(16B)
    int br = tid >> 2, bc0 = (tid & 3) * 4;       // B: 64 rows x 16 chunks(16B)
    const __nv_bfloat16* Ag = A + (size_t)(m0 + ar) * Kd + ac0 * 8;
    const __nv_bfloat16* Wg = W + (size_t)br * NH + n0 + bc0 * 8;

    float acc[2][8][4] = {};

    for (int k0 = 0; k0 < Kd; k0 += 64) {
        uint4 av[4], bv[4];
        #pragma unroll
        for (int i = 0; i < 4; i++) av[i] = *(const uint4*)(Ag + k0 + i * 8);
        #pragma unroll
        for (int i = 0; i < 4; i++) bv[i] = *(const uint4*)(Wg + (size_t)k0 * NH + i * 8);
        __syncthreads();
        #pragma unroll
        for (int i = 0; i < 4; i++) {
            int c = ac0 + i;
            *(uint4*)(As + ar * 64 + ((c ^ (ar & 7)) * 8)) = av[i];
        }
        #pragma unroll
        for (int i = 0; i < 4; i++) {
            int c = bc0 + i;
            int cs = (c & 8) | ((c & 7) ^ (br & 7));
            *(uint4*)(Bs + br * 128 + cs * 8) = bv[i];
        }
        __syncthreads();

        #pragma unroll
        for (int k16 = 0; k16 < 4; k16++) {
            unsigned afr[2][4], bfr[4][4];
            #pragma unroll
            for (int mi = 0; mi < 2; mi++) {
                int row = wm + mi * 16 + (lane & 15);
                int c = k16 * 2 + (lane >> 4);
                ldsm4(afr[mi], as_u + (row * 64 + ((c ^ (row & 7)) * 8)) * 2);
            }
            #pragma unroll
            for (int ni = 0; ni < 4; ni++) {
                int krow = k16 * 16 + (lane & 15);
                int c = (wn >> 3) + ni * 2 + (lane >> 4);
                int cs = (c & 8) | ((c & 7) ^ (krow & 7));
                ldsm4t(bfr[ni], bs_u + (krow * 128 + cs * 8) * 2);
            }
            #pragma unroll
            for (int mi = 0; mi < 2; mi++)
                #pragma unroll
                for (int ni = 0; ni < 4; ni++) {
                    mma16816(acc[mi][ni * 2],     afr[mi], bfr[ni][0], bfr[ni][1]);
                    mma16816(acc[mi][ni * 2 + 1], afr[mi], bfr[ni][2], bfr[ni][3]);
                }
        }
    }

    // epilogue
    int rr = lane >> 2, cc = (lane & 3) * 2;
    #pragma unroll
    for (int mi = 0; mi < 2; mi++) {
        int gm = m0 + wm + mi * 16 + rr;
        #pragma unroll
        for (int ni = 0; ni < 8; ni++) {
            int gn = n0 + wn + ni * 8 + cc;
            float b0 = bias[gn], b1 = bias[gn + 1];
            float v0 = acc[mi][ni][0] + b0;
            float v1 = acc[mi][ni][1] + b1;
            float v2 = acc[mi][ni][2] + b0;
            float v3 = acc[mi][ni][3] + b1;
            if (MODE == 0) {
                v0 = fmaxf(v0, 0.f); v1 = fmaxf(v1, 0.f);
                v2 = fmaxf(v2, 0.f); v3 = fmaxf(v3, 0.f);
                *(__nv_bfloat162*)&g_hb[(size_t)gm * NH + gn]       = __floats2bfloat162_rn(v0, v1);
                *(__nv_bfloat162*)&g_hb[(size_t)(gm + 8) * NH + gn] = __floats2bfloat162_rn(v2, v3);
            } else {
                float p0 = pa[gn], p1 = pa[gn + 1];
                v0 = (v0 > 0.f) ? v0 : p0 * v0;
                v1 = (v1 > 0.f) ? v1 : p1 * v1;
                v2 = (v2 > 0.f) ? v2 : p0 * v2;
                v3 = (v3 > 0.f) ? v3 : p1 * v3;
                g_h1[(size_t)gm * NH + gn]           = v0;
                g_h1[(size_t)gm * NH + gn + 1]       = v1;
                g_h1[(size_t)(gm + 8) * NH + gn]     = v2;
                g_h1[(size_t)(gm + 8) * NH + gn + 1] = v3;
            }
        }
    }
}

// logits = h1 @ w2 + b2 ; softmax over 2
__global__ void fc2_softmax_k(const float* __restrict__ w2,
                              const float* __restrict__ b2,
                              float* __restrict__ out) {
    int gw = (blockIdx.x * blockDim.x + threadIdx.x) >> 5;
    int lane = threadIdx.x & 31;
    int nw = (gridDim.x * blockDim.x) >> 5;
    for (int r = gw; r < RWS; r += nw) {
        const float* h = g_h1 + (size_t)r * NH;
        float s0 = 0.f, s1 = 0.f;
        #pragma unroll
        for (int i = lane; i < NH; i += 32) {
            float v = h[i];
            s0 += v * w2[2 * i];
            s1 += v * w2[2 * i + 1];
        }
        #pragma unroll
        for (int o = 16; o; o >>= 1) {
            s0 += __shfl_xor_sync(0xffffffffu, s0, o);
            s1 += __shfl_xor_sync(0xffffffffu, s1, o);
        }
        if (lane == 0) {
            float l0 = s0 + b2[0], l1 = s1 + b2[1];
            float m = fmaxf(l0, l1);
            float e0 = expf(l0 - m), e1 = expf(l1 - m);
            float inv = 1.f / (e0 + e1);
            out[2 * r] = e0 * inv;
            out[2 * r + 1] = e1 * inv;
        }
    }
}

// ---------------- launch ----------------
extern "C" void kernel_launch(void* const* d_in, const int* in_sizes, int n_in,
                              void* d_out, int out_size) {
    const int*   indexes  = (const int*)d_in[0];
    const float* features = (const float*)d_in[1];
    const int*   labels   = (const int*)d_in[2];
    const int*   nbr      = (const int*)d_in[3];
    const float* conv_w   = (const float*)d_in[4];
    const float* conv_b   = (const float*)d_in[5];
    const float* w1       = (const float*)d_in[6];
    const float* b1       = (const float*)d_in[7];
    const float* pa       = (const float*)d_in[8];
    const float* w2       = (const float*)d_in[9];
    const float* b2       = (const float*)d_in[10];
    float* out = (float*)d_out;

    zero_counts_k<<<NCn / 256, 256>>>();
    count_k<<<Np / 256, 256>>>(labels);
    scan_k<<<1, 1024>>>();
    scatter_k<<<Np / 256, 256>>>(labels);
    sortbucket_k<<<(NCn + 255) / 256, 256>>>();
    clumean_k<<<dim3(Dn / 256, NCn), 256>>>(features);
    convw_k<<<(CDn * NH + 255) / 256, 256>>>(conv_w, w1);
    build_cf_k<<<RWS, 256>>>(indexes, features, labels, nbr);
    a_k<<<dim3(8, Bn), 256>>>();
    a_reduce_k<<<(Bn * 4096) / 256, 256>>>();
    mask_k<<<Bn, 64>>>(labels, nbr);
    norm_k<<<RWS, 256>>>();
    q_k<<<Bn, 256>>>();
    center_k<<<RWS, 256>>>();
    agg_k<<<dim3(Dn / 64, Bn), 256>>>();
    mgemm_k<0><<<dim3(NH / 128, RWS / 128), 256>>>(conv_b, nullptr);
    mgemm_k<1><<<dim3(NH / 128, RWS / 128), 256>>>(b1, pa);
    fc2_softmax_k<<<64, 256>>>(w2, b2, out);
}

// round 4
// speedup vs baseline: 2.5276x; 1.1823x over previous
#include <cuda_runtime.h>
#include <cuda_bf16.h>
#include <stdint.h>
#include <cstdint>
#include <math.h>

// ---------------- problem constants ----------------
#define Bn   64
#define Kn   64
#define Np   32768
#define Dn   2048
#define NCn  2048
#define NH   512
#define CDn  4096      // 2*Dn
#define RWS  4096      // Bn*Kn

// ---------------- device scratch ----------------
__device__ int   g_counts[NCn];
__device__ int   g_offsets[NCn + 1];
__device__ int   g_cursor[NCn];
__device__ int   g_bucket[Np];
__device__ float g_clu[(size_t)NCn * Dn];          // 16 MB cluster means
__device__ float g_x[(size_t)RWS * Dn];            // 32 MB fp32 raw cf
__device__ __nv_bfloat16 g_catb[(size_t)RWS * CDn];// 32 MB bf16 [x | agg]
__device__ __nv_bfloat16 g_adjb[RWS * Kn];         // 0.5 MB bf16 masked adj
__device__ float g_apart[8 * Bn * Kn * Kn];        // 8 MB split-K partials
__device__ float g_rinv[RWS];
__device__ float g_q[Bn * Dn];
__device__ __nv_bfloat16 g_hb[(size_t)RWS * NH];   // 4 MB
__device__ float g_h1[(size_t)RWS * NH];           // 8 MB
__device__ __nv_bfloat16 g_wb[(size_t)CDn * NH];   // 4 MB
__device__ __nv_bfloat16 g_w1b[NH * NH];           // 0.5 MB

// ---------------- cluster mean via deterministic bucketing ----------------
__global__ void zero_counts_k() {
    int i = blockIdx.x * blockDim.x + threadIdx.x;
    if (i < NCn) g_counts[i] = 0;
}

__global__ void count_k(const int* __restrict__ labels) {
    int n = blockIdx.x * blockDim.x + threadIdx.x;
    if (n < Np) atomicAdd(&g_counts[labels[n]], 1);
}

__global__ void scan_k() {
    __shared__ int s[NCn];
    int t = threadIdx.x;
    s[t]        = g_counts[t];
    s[t + 1024] = g_counts[t + 1024];
    __syncthreads();
    for (int off = 1; off < NCn; off <<= 1) {
        int v0 = (t >= off) ? s[t - off] : 0;
        int v1 = s[t + 1024 - off];
        __syncthreads();
        s[t]        += v0;
        s[t + 1024] += v1;
        __syncthreads();
    }
    g_offsets[t]        = (t == 0) ? 0 : s[t - 1];
    g_offsets[t + 1024] = s[t + 1023];
    if (t == 0) g_offsets[NCn] = s[NCn - 1];
    __syncthreads();
    g_cursor[t]        = g_offsets[t];
    g_cursor[t + 1024] = g_offsets[t + 1024];
}

__global__ void scatter_k(const int* __restrict__ labels) {
    int n = blockIdx.x * blockDim.x + threadIdx.x;
    if (n < Np) {
        int pos = atomicAdd(&g_cursor[labels[n]], 1);
        g_bucket[pos] = n;
    }
}

__global__ void sortbucket_k() {
    int c = blockIdx.x * blockDim.x + threadIdx.x;
    if (c >= NCn) return;
    int s = g_offsets[c], e = g_offsets[c + 1];
    for (int i = s + 1; i < e; i++) {
        int v = g_bucket[i];
        int j = i - 1;
        while (j >= s && g_bucket[j] > v) { g_bucket[j + 1] = g_bucket[j]; j--; }
        g_bucket[j + 1] = v;
    }
}

__global__ void clumean_k(const float* __restrict__ features) {
    int c = blockIdx.y;
    int d = blockIdx.x * 256 + threadIdx.x;
    int s = g_offsets[c], e = g_offsets[c + 1];
    float sum = 0.f;
    for (int m = s; m < e; ++m)
        sum += features[(size_t)g_bucket[m] * Dn + d];
    g_clu[(size_t)c * Dn + d] = sum / fmaxf((float)(e - s), 1.f);
}

// ---------------- weight conversion to bf16 ----------------
__global__ void convw_k(const float* __restrict__ w, const float* __restrict__ w1) {
    int i = blockIdx.x * 256 + threadIdx.x;
    if (i < CDn * NH) g_wb[i] = __float2bfloat16(w[i]);
    if (i < NH * NH)  g_w1b[i] = __float2bfloat16(w1[i]);
}

// ---------------- cf build + fused row-norm ----------------
__global__ void build_cf_norm_k(const int* __restrict__ indexes,
                                const float* __restrict__ features,
                                const int* __restrict__ labels,
                                const int* __restrict__ nbr) {
    int r = blockIdx.x, t = threadIdx.x;
    int b = r >> 6, k = r & 63;
    const float* src;
    if (k == 0) src = features + (size_t)indexes[b] * Dn;
    else        src = g_clu + (size_t)labels[nbr[r]] * Dn;
    const float4* s4 = (const float4*)src;
    float4* d4 = (float4*)(g_x + (size_t)r * Dn);
    float s = 0.f;
    #pragma unroll
    for (int i = t; i < Dn / 4; i += 256) {
        float4 v = s4[i];
        d4[i] = v;
        s += v.x * v.x + v.y * v.y + v.z * v.z + v.w * v.w;
    }
    __shared__ float red[8];
    #pragma unroll
    for (int o = 16; o; o >>= 1) s += __shfl_xor_sync(0xffffffffu, s, o);
    if ((t & 31) == 0) red[t >> 5] = s;
    __syncthreads();
    if (t < 8) {
        float v = red[t];
        #pragma unroll
        for (int o = 4; o; o >>= 1) v += __shfl_xor_sync(0xffu, v, o);
        if (t == 0) g_rinv[r] = 1.f / sqrtf(v);
    }
}

// A partial = cf cf^T over a K chunk of 256; grid (8, Bn)
__global__ void __launch_bounds__(256) a_k() {
    __shared__ float tile[64][65];
    int chunk = blockIdx.x, b = blockIdx.y, t = threadIdx.x;
    int tx = t & 15, ty = t >> 4;
    float acc[4][4] = {};
    for (int c0 = chunk * 256; c0 < chunk * 256 + 256; c0 += 64) {
        #pragma unroll
        for (int it = 0; it < 16; ++it) {
            int idx = t + 256 * it;
            int row = idx >> 6, col = idx & 63;
            tile[row][col] = g_x[(size_t)(b * 64 + row) * Dn + c0 + col];
        }
        __syncthreads();
        #pragma unroll 8
        for (int dc = 0; dc < 64; dc++) {
            float a0 = tile[ty * 4 + 0][dc], a1 = tile[ty * 4 + 1][dc];
            float a2 = tile[ty * 4 + 2][dc], a3 = tile[ty * 4 + 3][dc];
            float b0 = tile[tx * 4 + 0][dc], b1 = tile[tx * 4 + 1][dc];
            float b2 = tile[tx * 4 + 2][dc], b3 = tile[tx * 4 + 3][dc];
            acc[0][0] += a0 * b0; acc[0][1] += a0 * b1; acc[0][2] += a0 * b2; acc[0][3] += a0 * b3;
            acc[1][0] += a1 * b0; acc[1][1] += a1 * b1; acc[1][2] += a1 * b2; acc[1][3] += a1 * b3;
            acc[2][0] += a2 * b0; acc[2][1] += a2 * b1; acc[2][2] += a2 * b2; acc[2][3] += a2 * b3;
            acc[3][0] += a3 * b0; acc[3][1] += a3 * b1; acc[3][2] += a3 * b2; acc[3][3] += a3 * b3;
        }
        __syncthreads();
    }
    float* dst = g_apart + (size_t)(chunk * Bn + b) * 4096;
    #pragma unroll
    for (int ii = 0; ii < 4; ii++)
        #pragma unroll
        for (int jj = 0; jj < 4; jj++)
            dst[(ty * 4 + ii) * 64 + tx * 4 + jj] = acc[ii][jj];
}

// fused: reduce split-K partials -> keep/dup + mutual top-5 mask -> bf16 adj
__global__ void __launch_bounds__(256) maskred_k(const int* __restrict__ labels,
                                                 const int* __restrict__ nbr) {
    __shared__ float As[64][65];
    __shared__ unsigned long long rm[64];
    __shared__ int lab[64];
    __shared__ int keep[64];
    int b = blockIdx.x, t = threadIdx.x;   // 256 threads
    // phase 1: deterministic fixed-order reduce of 8 partials (+ /5)
    for (int loc = t; loc < 4096; loc += 256) {
        float s = 0.f;
        #pragma unroll
        for (int c = 0; c < 8; c++) s += g_apart[(size_t)(c * Bn + b) * 4096 + loc];
        As[loc >> 6][loc & 63] = s * 0.2f;
    }
    if (t < 64) lab[t] = labels[nbr[b * 64 + t]];
    __syncthreads();
    // phase 2: 64 active threads do keep + stable top-5 (lower index wins ties)
    if (t < 64) {
        int dup = 0;
        for (int j = 0; j < t; j++) dup |= (lab[j] == lab[t]);
        keep[t] = !dup;
        unsigned long long sel = 0ULL;
        for (int r = 0; r < 5; r++) {
            float best = -3.4e38f; int bi = 0;
            for (int j = 0; j < 64; j++) {
                float v = As[t][j];
                if (!((sel >> j) & 1ULL) && v > best) { best = v; bi = j; }
            }
            sel |= 1ULL << bi;
        }
        rm[t] = sel;
    }
    __syncthreads();
    if (t < 64) {
        bool kt = keep[t];
        for (int j = 0; j < 64; j++) {
            bool mm = kt && keep[j] && ((rm[t] >> j) & 1ULL) && ((rm[j] >> t) & 1ULL);
            g_adjb[(b * 64 + t) * 64 + j] = __float2bfloat16(mm ? As[t][j] : 0.f);
        }
    }
}

__global__ void q_k() {
    int b = blockIdx.x, t = threadIdx.x;
    float rv = g_rinv[b * 64];
    for (int d = t; d < Dn; d += 256)
        g_q[b * Dn + d] = g_x[(size_t)(b * 64) * Dn + d] * rv;
}

// x = cf/||cf|| - q ; write bf16 only (g_x stays raw for a_k)
__global__ void center_k() {
    int r = blockIdx.x, t = threadIdx.x;
    int b = r >> 6;
    float rv = g_rinv[r];
    for (int d = t; d < Dn; d += 256) {
        float v = g_x[(size_t)r * Dn + d] * rv - g_q[b * Dn + d];
        g_catb[(size_t)r * CDn + d] = __float2bfloat16(v);
    }
}

// ---------------- tensor-core helpers ----------------
__device__ __forceinline__ void ldsm4(unsigned* r, unsigned a) {
    asm volatile("ldmatrix.sync.aligned.m8n8.x4.shared.b16 {%0,%1,%2,%3}, [%4];"
        : "=r"(r[0]), "=r"(r[1]), "=r"(r[2]), "=r"(r[3]) : "r"(a));
}
__device__ __forceinline__ void ldsm4t(unsigned* r, unsigned a) {
    asm volatile("ldmatrix.sync.aligned.m8n8.x4.trans.shared.b16 {%0,%1,%2,%3}, [%4];"
        : "=r"(r[0]), "=r"(r[1]), "=r"(r[2]), "=r"(r[3]) : "r"(a));
}
__device__ __forceinline__ void mma16816(float* c, const unsigned* a, unsigned b0, unsigned b1) {
    asm volatile("mma.sync.aligned.m16n8k16.row.col.f32.bf16.bf16.f32 "
        "{%0,%1,%2,%3}, {%4,%5,%6,%7}, {%8,%9}, {%0,%1,%2,%3};"
        : "+f"(c[0]), "+f"(c[1]), "+f"(c[2]), "+f"(c[3])
        : "r"(a[0]), "r"(a[1]), "r"(a[2]), "r"(a[3]), "r"(b0), "r"(b1));
}
__device__ __forceinline__ void cpasync16(unsigned dst, const void* src) {
    asm volatile("cp.async.cg.shared.global [%0], [%1], 16;"
        :: "r"(dst), "l"(__cvta_generic_to_global(src)));
}
__device__ __forceinline__ void cpcommit() {
    asm volatile("cp.async.commit_group;");
}

// agg = adj @ x on tensor cores -> g_catb[:, Dn:2Dn]; grid (Dn/128, Bn), 128 thr
__global__ void __launch_bounds__(128) bagg_k() {
    __shared__ __nv_bfloat16 Aj[64 * 64];
    __shared__ __nv_bfloat16 Xs[64 * 128];
    int b = blockIdx.y, d0 = blockIdx.x * 128;
    int tid = threadIdx.x, lane = tid & 31, warp = tid >> 5;
    int wn = warp * 32;
    unsigned aj_u = (unsigned)__cvta_generic_to_shared(Aj);
    unsigned xs_u = (unsigned)__cvta_generic_to_shared(Xs);

    // load adj (64x64) swizzled
    {
        int ar = tid >> 1, ac0 = (tid & 1) * 4;
        const __nv_bfloat16* src = g_adjb + (size_t)(b * 64 + ar) * 64 + ac0 * 8;
        #pragma unroll
        for (int i = 0; i < 4; i++) {
            uint4 v = *(const uint4*)(src + i * 8);
            int c = ac0 + i;
            *(uint4*)(Aj + ar * 64 + ((c ^ (ar & 7)) * 8)) = v;
        }
    }
    // load x tile (64 rows k, 128 cols n) swizzled
    {
        int br = tid >> 2, bc0 = (tid & 3) * 4;
        #pragma unroll
        for (int h = 0; h < 64; h += 32) {
            int row = br + h;
            const __nv_bfloat16* src = g_catb + (size_t)(b * 64 + row) * CDn + d0 + bc0 * 8;
            #pragma unroll
            for (int i = 0; i < 4; i++) {
                uint4 v = *(const uint4*)(src + i * 8);
                int c = bc0 + i;
                int cs = (c & 8) | ((c & 7) ^ (row & 7));
                *(uint4*)(Xs + row * 128 + cs * 8) = v;
            }
        }
    }
    __syncthreads();

    float acc[4][4][4] = {};
    #pragma unroll
    for (int k16 = 0; k16 < 4; k16++) {
        unsigned afr[4][4], bfr[2][4];
        #pragma unroll
        for (int mi = 0; mi < 4; mi++) {
            int row = mi * 16 + (lane & 15);
            int c = k16 * 2 + (lane >> 4);
            ldsm4(afr[mi], aj_u + (row * 64 + ((c ^ (row & 7)) * 8)) * 2);
        }
        #pragma unroll
        for (int ni = 0; ni < 2; ni++) {
            int krow = k16 * 16 + (lane & 15);
            int c = (wn >> 3) + ni * 2 + (lane >> 4);
            int cs = (c & 8) | ((c & 7) ^ (krow & 7));
            ldsm4t(bfr[ni], xs_u + (krow * 128 + cs * 8) * 2);
        }
        #pragma unroll
        for (int mi = 0; mi < 4; mi++)
            #pragma unroll
            for (int ni = 0; ni < 2; ni++) {
                mma16816(acc[mi][ni * 2],     afr[mi], bfr[ni][0], bfr[ni][1]);
                mma16816(acc[mi][ni * 2 + 1], afr[mi], bfr[ni][2], bfr[ni][3]);
            }
    }
    int rr = lane >> 2, cc = (lane & 3) * 2;
    #pragma unroll
    for (int mi = 0; mi < 4; mi++) {
        int gm = mi * 16 + rr;
        #pragma unroll
        for (int ni = 0; ni < 4; ni++) {
            int gn = wn + ni * 8 + cc;
            size_t base0 = (size_t)(b * 64 + gm) * CDn + Dn + d0 + gn;
            size_t base1 = (size_t)(b * 64 + gm + 8) * CDn + Dn + d0 + gn;
            *(__nv_bfloat162*)&g_catb[base0] = __floats2bfloat162_rn(acc[mi][ni][0], acc[mi][ni][1]);
            *(__nv_bfloat162*)&g_catb[base1] = __floats2bfloat162_rn(acc[mi][ni][2], acc[mi][ni][3]);
        }
    }
}

// ---------------- pipelined bf16 tensor-core GEMMs (cp.async 2-stage) ----------------
// BM=128, BN=128, BK=64; 256 threads = 8 warps (4M x 2N).
// MODE 0: h = relu(catb @ wb + conv_b)   -> g_hb (bf16), K=4096
// MODE 1: h1 = prelu(hb @ w1b + b1, pa)  -> g_h1 (fp32), K=512
template <int MODE>
__global__ void __launch_bounds__(256) mgemm_k(const float* __restrict__ bias,
                                               const float* __restrict__ pa) {
    constexpr int Kd = (MODE == 0) ? CDn : NH;
    const __nv_bfloat16* A = (MODE == 0) ? g_catb : g_hb;
    const __nv_bfloat16* W = (MODE == 0) ? g_wb : g_w1b;
    extern __shared__ __nv_bfloat16 smem[];
    // layout: [As stage0 | As stage1 | Bs stage0 | Bs stage1], each 8192 elems
    int tid = threadIdx.x;
    int lane = tid & 31, warp = tid >> 5;
    int wm = (warp & 3) * 32, wn = (warp >> 2) * 64;
    int m0 = blockIdx.y * 128, n0 = blockIdx.x * 128;
    unsigned as_u = (unsigned)__cvta_generic_to_shared(smem);
    unsigned bs_u = as_u + 2 * 8192 * 2;

    int ar = tid >> 1, ac0 = (tid & 1) * 4;       // A: 128 rows x 8 chunks(16B)
    int br = tid >> 2, bc0 = (tid & 3) * 4;       // B: 64 rows x 16 chunks(16B)
    const __nv_bfloat16* Ag = A + (size_t)(m0 + ar) * Kd + ac0 * 8;
    const __nv_bfloat16* Wg = W + (size_t)br * NH + n0 + bc0 * 8;

    auto issue = [&](int k0, int s) {
        unsigned as_s = as_u + (unsigned)(s * 16384);
        unsigned bs_s = bs_u + (unsigned)(s * 16384);
        #pragma unroll
        for (int i = 0; i < 4; i++) {
            int c = ac0 + i;
            cpasync16(as_s + (unsigned)((ar * 64 + ((c ^ (ar & 7)) * 8)) * 2),
                      Ag + k0 + i * 8);
        }
        #pragma unroll
        for (int i = 0; i < 4; i++) {
            int c = bc0 + i;
            int cs = (c & 8) | ((c & 7) ^ (br & 7));
            cpasync16(bs_s + (unsigned)((br * 128 + cs * 8) * 2),
                      Wg + (size_t)k0 * NH + i * 8);
        }
        cpcommit();
    };

    float acc[2][8][4] = {};
    constexpr int nk = Kd / 64;
    issue(0, 0);
    for (int it = 0; it < nk; it++) {
        int s = it & 1;
        if (it + 1 < nk) {
            issue((it + 1) * 64, (it + 1) & 1);
            asm volatile("cp.async.wait_group 1;");
        } else {
            asm volatile("cp.async.wait_group 0;");
        }
        __syncthreads();
        unsigned as_s = as_u + (unsigned)(s * 16384);
        unsigned bs_s = bs_u + (unsigned)(s * 16384);
        #pragma unroll
        for (int k16 = 0; k16 < 4; k16++) {
            unsigned afr[2][4], bfr[4][4];
            #pragma unroll
            for (int mi = 0; mi < 2; mi++) {
                int row = wm + mi * 16 + (lane & 15);
                int c = k16 * 2 + (lane >> 4);
                ldsm4(afr[mi], as_s + (row * 64 + ((c ^ (row & 7)) * 8)) * 2);
            }
            #pragma unroll
            for (int ni = 0; ni < 4; ni++) {
                int krow = k16 * 16 + (lane & 15);
                int c = (wn >> 3) + ni * 2 + (lane >> 4);
                int cs = (c & 8) | ((c & 7) ^ (krow & 7));
                ldsm4t(bfr[ni], bs_s + (krow * 128 + cs * 8) * 2);
            }
            #pragma unroll
            for (int mi = 0; mi < 2; mi++)
                #pragma unroll
                for (int ni = 0; ni < 4; ni++) {
                    mma16816(acc[mi][ni * 2],     afr[mi], bfr[ni][0], bfr[ni][1]);
                    mma16816(acc[mi][ni * 2 + 1], afr[mi], bfr[ni][2], bfr[ni][3]);
                }
        }
        __syncthreads();
    }

    // epilogue
    int rr = lane >> 2, cc = (lane & 3) * 2;
    #pragma unroll
    for (int mi = 0; mi < 2; mi++) {
        int gm = m0 + wm + mi * 16 + rr;
        #pragma unroll
        for (int ni = 0; ni < 8; ni++) {
            int gn = n0 + wn + ni * 8 + cc;
            float b0 = bias[gn], b1 = bias[gn + 1];
            float v0 = acc[mi][ni][0] + b0;
            float v1 = acc[mi][ni][1] + b1;
            float v2 = acc[mi][ni][2] + b0;
            float v3 = acc[mi][ni][3] + b1;
            if (MODE == 0) {
                v0 = fmaxf(v0, 0.f); v1 = fmaxf(v1, 0.f);
                v2 = fmaxf(v2, 0.f); v3 = fmaxf(v3, 0.f);
                *(__nv_bfloat162*)&g_hb[(size_t)gm * NH + gn]       = __floats2bfloat162_rn(v0, v1);
                *(__nv_bfloat162*)&g_hb[(size_t)(gm + 8) * NH + gn] = __floats2bfloat162_rn(v2, v3);
            } else {
                float p0 = pa[gn], p1 = pa[gn + 1];
                v0 = (v0 > 0.f) ? v0 : p0 * v0;
                v1 = (v1 > 0.f) ? v1 : p1 * v1;
                v2 = (v2 > 0.f) ? v2 : p0 * v2;
                v3 = (v3 > 0.f) ? v3 : p1 * v3;
                g_h1[(size_t)gm * NH + gn]           = v0;
                g_h1[(size_t)gm * NH + gn + 1]       = v1;
                g_h1[(size_t)(gm + 8) * NH + gn]     = v2;
                g_h1[(size_t)(gm + 8) * NH + gn + 1] = v3;
            }
        }
    }
}

// logits = h1 @ w2 + b2 ; softmax over 2
__global__ void fc2_softmax_k(const float* __restrict__ w2,
                              const float* __restrict__ b2,
                              float* __restrict__ out) {
    int gw = (blockIdx.x * blockDim.x + threadIdx.x) >> 5;
    int lane = threadIdx.x & 31;
    int nw = (gridDim.x * blockDim.x) >> 5;
    for (int r = gw; r < RWS; r += nw) {
        const float* h = g_h1 + (size_t)r * NH;
        float s0 = 0.f, s1 = 0.f;
        #pragma unroll
        for (int i = lane; i < NH; i += 32) {
            float v = h[i];
            s0 += v * w2[2 * i];
            s1 += v * w2[2 * i + 1];
        }
        #pragma unroll
        for (int o = 16; o; o >>= 1) {
            s0 += __shfl_xor_sync(0xffffffffu, s0, o);
            s1 += __shfl_xor_sync(0xffffffffu, s1, o);
        }
        if (lane == 0) {
            float l0 = s0 + b2[0], l1 = s1 + b2[1];
            float m = fmaxf(l0, l1);
            float e0 = expf(l0 - m), e1 = expf(l1 - m);
            float inv = 1.f / (e0 + e1);
            out[2 * r] = e0 * inv;
            out[2 * r + 1] = e1 * inv;
        }
    }
}

// ---------------- launch ----------------
extern "C" void kernel_launch(void* const* d_in, const int* in_sizes, int n_in,
                              void* d_out, int out_size) {
    const int*   indexes  = (const int*)d_in[0];
    const float* features = (const float*)d_in[1];
    const int*   labels   = (const int*)d_in[2];
    const int*   nbr      = (const int*)d_in[3];
    const float* conv_w   = (const float*)d_in[4];
    const float* conv_b   = (const float*)d_in[5];
    const float* w1       = (const float*)d_in[6];
    const float* b1       = (const float*)d_in[7];
    const float* pa       = (const float*)d_in[8];
    const float* w2       = (const float*)d_in[9];
    const float* b2       = (const float*)d_in[10];
    float* out = (float*)d_out;

    const int MGEMM_SMEM = 4 * 8192 * 2;   // 64 KB dynamic
    cudaFuncSetAttribute(mgemm_k<0>, cudaFuncAttributeMaxDynamicSharedMemorySize, MGEMM_SMEM);
    cudaFuncSetAttribute(mgemm_k<1>, cudaFuncAttributeMaxDynamicSharedMemorySize, MGEMM_SMEM);

    zero_counts_k<<<NCn / 256, 256>>>();
    count_k<<<Np / 256, 256>>>(labels);
    scan_k<<<1, 1024>>>();
    scatter_k<<<Np / 256, 256>>>(labels);
    sortbucket_k<<<(NCn + 255) / 256, 256>>>();
    clumean_k<<<dim3(Dn / 256, NCn), 256>>>(features);
    convw_k<<<(CDn * NH + 255) / 256, 256>>>(conv_w, w1);
    build_cf_norm_k<<<RWS, 256>>>(indexes, features, labels, nbr);
    a_k<<<dim3(8, Bn), 256>>>();
    maskred_k<<<Bn, 256>>>(labels, nbr);
    q_k<<<Bn, 256>>>();
    center_k<<<RWS, 256>>>();
    bagg_k<<<dim3(Dn / 128, Bn), 128>>>();
    mgemm_k<0><<<dim3(NH / 128, RWS / 128), 256, MGEMM_SMEM>>>(conv_b, nullptr);
    mgemm_k<1><<<dim3(NH / 128, RWS / 128), 256, MGEMM_SMEM>>>(b1, pa);
    fc2_softmax_k<<<64, 256>>>(w2, b2, out);
}

// round 5
// speedup vs baseline: 2.6164x; 1.0351x over previous
#include <cuda_runtime.h>
#include <cuda_bf16.h>
#include <stdint.h>
#include <cstdint>
#include <math.h>

// ---------------- problem constants ----------------
#define Bn   64
#define Kn   64
#define Np   32768
#define Dn   2048
#define NCn  2048
#define NH   512
#define CDn  4096      // 2*Dn
#define RWS  4096      // Bn*Kn

// ---------------- device scratch ----------------
__device__ int   g_counts[NCn];
__device__ int   g_offsets[NCn + 1];
__device__ int   g_cursor[NCn];
__device__ int   g_bucket[Np];
__device__ float g_clu[(size_t)NCn * Dn];          // 16 MB cluster means
__device__ float g_x[(size_t)RWS * Dn];            // 32 MB fp32 raw cf
__device__ __nv_bfloat16 g_catb[(size_t)RWS * CDn];// 32 MB bf16 [x | agg]
__device__ float g_adj[RWS * Kn];                  // 1 MB fp32 raw A
__device__ __nv_bfloat16 g_adjb[RWS * Kn];         // 0.5 MB bf16 masked adj
__device__ float g_rinv[RWS];
__device__ __nv_bfloat16 g_hb[(size_t)RWS * NH];   // 4 MB
__device__ float g_h1[(size_t)RWS * NH];           // 8 MB
__device__ __nv_bfloat16 g_wb[(size_t)CDn * NH];   // 4 MB
__device__ __nv_bfloat16 g_w1b[NH * NH];           // 0.5 MB

// ---------------- cluster mean via deterministic bucketing ----------------
__global__ void zero_counts_k() {
    int i = blockIdx.x * blockDim.x + threadIdx.x;
    if (i < NCn) g_counts[i] = 0;
}

__global__ void count_k(const int* __restrict__ labels) {
    int n = blockIdx.x * blockDim.x + threadIdx.x;
    if (n < Np) atomicAdd(&g_counts[labels[n]], 1);
}

__global__ void scan_k() {
    __shared__ int s[NCn];
    int t = threadIdx.x;
    s[t]        = g_counts[t];
    s[t + 1024] = g_counts[t + 1024];
    __syncthreads();
    for (int off = 1; off < NCn; off <<= 1) {
        int v0 = (t >= off) ? s[t - off] : 0;
        int v1 = s[t + 1024 - off];
        __syncthreads();
        s[t]        += v0;
        s[t + 1024] += v1;
        __syncthreads();
    }
    g_offsets[t]        = (t == 0) ? 0 : s[t - 1];
    g_offsets[t + 1024] = s[t + 1023];
    if (t == 0) g_offsets[NCn] = s[NCn - 1];
    __syncthreads();
    g_cursor[t]        = g_offsets[t];
    g_cursor[t + 1024] = g_offsets[t + 1024];
}

__global__ void scatter_k(const int* __restrict__ labels) {
    int n = blockIdx.x * blockDim.x + threadIdx.x;
    if (n < Np) {
        int pos = atomicAdd(&g_cursor[labels[n]], 1);
        g_bucket[pos] = n;
    }
}

__global__ void sortbucket_k() {
    int c = blockIdx.x * blockDim.x + threadIdx.x;
    if (c >= NCn) return;
    int s = g_offsets[c], e = g_offsets[c + 1];
    for (int i = s + 1; i < e; i++) {
        int v = g_bucket[i];
        int j = i - 1;
        while (j >= s && g_bucket[j] > v) { g_bucket[j + 1] = g_bucket[j]; j--; }
        g_bucket[j + 1] = v;
    }
}

__global__ void clumean_k(const float* __restrict__ features) {
    int c = blockIdx.y;
    int d = blockIdx.x * 256 + threadIdx.x;
    int s = g_offsets[c], e = g_offsets[c + 1];
    float sum = 0.f;
    for (int m = s; m < e; ++m)
        sum += features[(size_t)g_bucket[m] * Dn + d];
    g_clu[(size_t)c * Dn + d] = sum / fmaxf((float)(e - s), 1.f);
}

// ---------------- weight conversion to bf16 ----------------
__global__ void convw_k(const float* __restrict__ w, const float* __restrict__ w1) {
    int i = blockIdx.x * 256 + threadIdx.x;
    if (i < CDn * NH) g_wb[i] = __float2bfloat16(w[i]);
    if (i < NH * NH)  g_w1b[i] = __float2bfloat16(w1[i]);
}

// ---------------- cf build + fused row-norm ----------------
__global__ void build_cf_norm_k(const int* __restrict__ indexes,
                                const float* __restrict__ features,
                                const int* __restrict__ labels,
                                const int* __restrict__ nbr) {
    int r = blockIdx.x, t = threadIdx.x;
    int b = r >> 6, k = r & 63;
    const float* src;
    if (k == 0) src = features + (size_t)indexes[b] * Dn;
    else        src = g_clu + (size_t)labels[nbr[r]] * Dn;
    const float4* s4 = (const float4*)src;
    float4* d4 = (float4*)(g_x + (size_t)r * Dn);
    float s = 0.f;
    #pragma unroll
    for (int i = t; i < Dn / 4; i += 256) {
        float4 v = s4[i];
        d4[i] = v;
        s += v.x * v.x + v.y * v.y + v.z * v.z + v.w * v.w;
    }
    __shared__ float red[8];
    #pragma unroll
    for (int o = 16; o; o >>= 1) s += __shfl_xor_sync(0xffffffffu, s, o);
    if ((t & 31) == 0) red[t >> 5] = s;
    __syncthreads();
    if (t < 8) {
        float v = red[t];
        #pragma unroll
        for (int o = 4; o; o >>= 1) v += __shfl_xor_sync(0xffu, v, o);
        if (t == 0) g_rinv[r] = 1.f / sqrtf(v);
    }
}

// ---------------- tensor-core helpers ----------------
__device__ __forceinline__ void ldsm4(unsigned* r, unsigned a) {
    asm volatile("ldmatrix.sync.aligned.m8n8.x4.shared.b16 {%0,%1,%2,%3}, [%4];"
        : "=r"(r[0]), "=r"(r[1]), "=r"(r[2]), "=r"(r[3]) : "r"(a));
}
__device__ __forceinline__ void ldsm4t(unsigned* r, unsigned a) {
    asm volatile("ldmatrix.sync.aligned.m8n8.x4.trans.shared.b16 {%0,%1,%2,%3}, [%4];"
        : "=r"(r[0]), "=r"(r[1]), "=r"(r[2]), "=r"(r[3]) : "r"(a));
}
__device__ __forceinline__ void mma16816(float* c, const unsigned* a, unsigned b0, unsigned b1) {
    asm volatile("mma.sync.aligned.m16n8k16.row.col.f32.bf16.bf16.f32 "
        "{%0,%1,%2,%3}, {%4,%5,%6,%7}, {%8,%9}, {%0,%1,%2,%3};"
        : "+f"(c[0]), "+f"(c[1]), "+f"(c[2]), "+f"(c[3])
        : "r"(a[0]), "r"(a[1]), "r"(a[2]), "r"(a[3]), "r"(b0), "r"(b1));
}
__device__ __forceinline__ void cpasync16(unsigned dst, const void* src) {
    asm volatile("cp.async.cg.shared.global [%0], [%1], 16;"
        :: "r"(dst), "l"(__cvta_generic_to_global(src)));
}
__device__ __forceinline__ void cpcommit() {
    asm volatile("cp.async.commit_group;");
}

// ---------------- A = cf cf^T / 5 on tensor cores via split-bf16 ----------------
// one block per sample; C = Xhi Xhi^T + Xhi Xlo^T + Xlo Xhi^T (fp32 acc)
// 8 warps (4 m x 2 n), warp tile 16x32, K pipelined by register double-buffer.
__global__ void __launch_bounds__(256) absplit_k() {
    __shared__ __nv_bfloat16 Shi[2][64 * 64];
    __shared__ __nv_bfloat16 Slo[2][64 * 64];
    int b = blockIdx.x, tid = threadIdx.x;
    int lane = tid & 31, warp = tid >> 5;
    int wm = (warp & 3) * 16, wn = (warp >> 2) * 32;
    unsigned hi_u = (unsigned)__cvta_generic_to_shared(Shi);
    unsigned lo_u = (unsigned)__cvta_generic_to_shared(Slo);

    int lr = tid >> 2;             // 0..63 loader row
    int lc = (tid & 3) * 16;       // loader col base
    const float* src = g_x + (size_t)(b * 64 + lr) * Dn + lc;

    float f[16];
    float acc[4][4] = {};

    // prefetch tile 0
    {
        const float4* p = (const float4*)src;
        #pragma unroll
        for (int i = 0; i < 4; i++) *(float4*)&f[i * 4] = p[i];
    }

    for (int t = 0; t < Dn / 64; t++) {
        int s = t & 1;
        // convert + swizzled store
        {
            __nv_bfloat16 h[16], l[16];
            #pragma unroll
            for (int i = 0; i < 16; i++) {
                h[i] = __float2bfloat16(f[i]);
                l[i] = __float2bfloat16(f[i] - __bfloat162float(h[i]));
            }
            int c0 = lc >> 3;
            #pragma unroll
            for (int half = 0; half < 2; half++) {
                int c = c0 + half;
                int off = lr * 64 + ((c ^ (lr & 7)) * 8);
                uint4 uh, ul;
                __nv_bfloat162 t2;
                t2 = __nv_bfloat162(h[half * 8 + 0], h[half * 8 + 1]); uh.x = *(unsigned*)&t2;
                t2 = __nv_bfloat162(h[half * 8 + 2], h[half * 8 + 3]); uh.y = *(unsigned*)&t2;
                t2 = __nv_bfloat162(h[half * 8 + 4], h[half * 8 + 5]); uh.z = *(unsigned*)&t2;
                t2 = __nv_bfloat162(h[half * 8 + 6], h[half * 8 + 7]); uh.w = *(unsigned*)&t2;
                t2 = __nv_bfloat162(l[half * 8 + 0], l[half * 8 + 1]); ul.x = *(unsigned*)&t2;
                t2 = __nv_bfloat162(l[half * 8 + 2], l[half * 8 + 3]); ul.y = *(unsigned*)&t2;
                t2 = __nv_bfloat162(l[half * 8 + 4], l[half * 8 + 5]); ul.z = *(unsigned*)&t2;
                t2 = __nv_bfloat162(l[half * 8 + 6], l[half * 8 + 7]); ul.w = *(unsigned*)&t2;
                *(uint4*)&Shi[s][off] = uh;
                *(uint4*)&Slo[s][off] = ul;
            }
        }
        __syncthreads();
        // prefetch next tile
        if (t + 1 < Dn / 64) {
            const float4* p = (const float4*)(src + (t + 1) * 64);
            #pragma unroll
            for (int i = 0; i < 4; i++) *(float4*)&f[i * 4] = p[i];
        }
        // compute on stage s
        unsigned base_h = hi_u + (unsigned)(s * 8192);
        unsigned base_l = lo_u + (unsigned)(s * 8192);
        #pragma unroll
        for (int k16 = 0; k16 < 4; k16++) {
            unsigned ahi[4], alo[4], bh[2][4], bl[2][4];
            int ac = k16 * 2 + (lane >> 4);
            int arow = wm + (lane & 15);
            unsigned aoff = (unsigned)((arow * 64 + ((ac ^ (arow & 7)) * 8)) * 2);
            ldsm4(ahi, base_h + aoff);
            ldsm4(alo, base_l + aoff);
            #pragma unroll
            for (int nt = 0; nt < 2; nt++) {
                int brow = wn + nt * 16 + (lane & 15);
                unsigned boff = (unsigned)((brow * 64 + ((ac ^ (brow & 7)) * 8)) * 2);
                ldsm4(bh[nt], base_h + boff);   // non-trans: X is n-major = col-major B
                ldsm4(bl[nt], base_l + boff);
            }
            #pragma unroll
            for (int nt = 0; nt < 2; nt++) {
                // x4 load covers n16: first n8 -> regs (0,2), second n8 -> regs (1,3)
                mma16816(acc[nt * 2 + 0], ahi, bh[nt][0], bh[nt][2]);
                mma16816(acc[nt * 2 + 0], ahi, bl[nt][0], bl[nt][2]);
                mma16816(acc[nt * 2 + 0], alo, bh[nt][0], bh[nt][2]);
                mma16816(acc[nt * 2 + 1], ahi, bh[nt][1], bh[nt][3]);
                mma16816(acc[nt * 2 + 1], ahi, bl[nt][1], bl[nt][3]);
                mma16816(acc[nt * 2 + 1], alo, bh[nt][1], bh[nt][3]);
            }
        }
        __syncthreads();
    }

    // epilogue: write C/5 fp32
    int gid = lane >> 2, tid4 = lane & 3;
    #pragma unroll
    for (int t = 0; t < 4; t++) {
        int n = wn + t * 8 + tid4 * 2;
        int m = wm + gid;
        g_adj[(b * 64 + m) * 64 + n]         = acc[t][0] * 0.2f;
        g_adj[(b * 64 + m) * 64 + n + 1]     = acc[t][1] * 0.2f;
        g_adj[(b * 64 + m + 8) * 64 + n]     = acc[t][2] * 0.2f;
        g_adj[(b * 64 + m + 8) * 64 + n + 1] = acc[t][3] * 0.2f;
    }
}

// keep-mask + mutual top-5 mask (fp32 in, bf16 adj out)
__global__ void mask_k(const int* __restrict__ labels, const int* __restrict__ nbr) {
    __shared__ float As[64][65];
    __shared__ unsigned long long rm[64];
    __shared__ int lab[64];
    __shared__ int keep[64];
    int b = blockIdx.x, t = threadIdx.x;   // 64 threads
    lab[t] = labels[nbr[b * 64 + t]];
    for (int it = 0; it < 64; it++)
        As[it][t] = g_adj[(b * 64 + it) * 64 + t];
    __syncthreads();
    int dup = 0;
    for (int j = 0; j < t; j++) dup |= (lab[j] == lab[t]);
    keep[t] = !dup;
    unsigned long long sel = 0ULL;
    for (int r = 0; r < 5; r++) {
        float best = -3.4e38f; int bi = 0;
        for (int j = 0; j < 64; j++) {
            float v = As[t][j];
            if (!((sel >> j) & 1ULL) && v > best) { best = v; bi = j; }
        }
        sel |= 1ULL << bi;
    }
    rm[t] = sel;
    __syncthreads();
    bool kt = keep[t];
    for (int j = 0; j < 64; j++) {
        bool mm = kt && keep[j] && ((rm[t] >> j) & 1ULL) && ((rm[j] >> t) & 1ULL);
        g_adjb[(b * 64 + t) * 64 + j] = __float2bfloat16(mm ? As[t][j] : 0.f);
    }
}

// x = cf/||cf|| - q (q computed inline; row 0 cancels exactly)
__global__ void center_k() {
    int r = blockIdx.x, t = threadIdx.x;
    int b = r >> 6;
    float rv = g_rinv[r];
    float qv = g_rinv[b * 64];
    const float* xr = g_x + (size_t)r * Dn;
    const float* xq = g_x + (size_t)(b * 64) * Dn;
    for (int d = t; d < Dn; d += 256) {
        float v = xr[d] * rv - xq[d] * qv;
        g_catb[(size_t)r * CDn + d] = __float2bfloat16(v);
    }
}

// agg = adj @ x on tensor cores -> g_catb[:, Dn:2Dn]; grid (Dn/128, Bn), 128 thr
__global__ void __launch_bounds__(128) bagg_k() {
    __shared__ __nv_bfloat16 Aj[64 * 64];
    __shared__ __nv_bfloat16 Xs[64 * 128];
    int b = blockIdx.y, d0 = blockIdx.x * 128;
    int tid = threadIdx.x, lane = tid & 31, warp = tid >> 5;
    int wn = warp * 32;
    unsigned aj_u = (unsigned)__cvta_generic_to_shared(Aj);
    unsigned xs_u = (unsigned)__cvta_generic_to_shared(Xs);

    {
        int ar = tid >> 1, ac0 = (tid & 1) * 4;
        const __nv_bfloat16* src = g_adjb + (size_t)(b * 64 + ar) * 64 + ac0 * 8;
        #pragma unroll
        for (int i = 0; i < 4; i++) {
            uint4 v = *(const uint4*)(src + i * 8);
            int c = ac0 + i;
            *(uint4*)(Aj + ar * 64 + ((c ^ (ar & 7)) * 8)) = v;
        }
    }
    {
        int br = tid >> 2, bc0 = (tid & 3) * 4;
        #pragma unroll
        for (int h = 0; h < 64; h += 32) {
            int row = br + h;
            const __nv_bfloat16* src = g_catb + (size_t)(b * 64 + row) * CDn + d0 + bc0 * 8;
            #pragma unroll
            for (int i = 0; i < 4; i++) {
                uint4 v = *(const uint4*)(src + i * 8);
                int c = bc0 + i;
                int cs = (c & 8) | ((c & 7) ^ (row & 7));
                *(uint4*)(Xs + row * 128 + cs * 8) = v;
            }
        }
    }
    __syncthreads();

    float acc[4][4][4] = {};
    #pragma unroll
    for (int k16 = 0; k16 < 4; k16++) {
        unsigned afr[4][4], bfr[2][4];
        #pragma unroll
        for (int mi = 0; mi < 4; mi++) {
            int row = mi * 16 + (lane & 15);
            int c = k16 * 2 + (lane >> 4);
            ldsm4(afr[mi], aj_u + (row * 64 + ((c ^ (row & 7)) * 8)) * 2);
        }
        #pragma unroll
        for (int ni = 0; ni < 2; ni++) {
            int krow = k16 * 16 + (lane & 15);
            int c = (wn >> 3) + ni * 2 + (lane >> 4);
            int cs = (c & 8) | ((c & 7) ^ (krow & 7));
            ldsm4t(bfr[ni], xs_u + (krow * 128 + cs * 8) * 2);
        }
        #pragma unroll
        for (int mi = 0; mi < 4; mi++)
            #pragma unroll
            for (int ni = 0; ni < 2; ni++) {
                mma16816(acc[mi][ni * 2],     afr[mi], bfr[ni][0], bfr[ni][1]);
                mma16816(acc[mi][ni * 2 + 1], afr[mi], bfr[ni][2], bfr[ni][3]);
            }
    }
    int rr = lane >> 2, cc = (lane & 3) * 2;
    #pragma unroll
    for (int mi = 0; mi < 4; mi++) {
        int gm = mi * 16 + rr;
        #pragma unroll
        for (int ni = 0; ni < 4; ni++) {
            int gn = wn + ni * 8 + cc;
            size_t base0 = (size_t)(b * 64 + gm) * CDn + Dn + d0 + gn;
            size_t base1 = (size_t)(b * 64 + gm + 8) * CDn + Dn + d0 + gn;
            *(__nv_bfloat162*)&g_catb[base0] = __floats2bfloat162_rn(acc[mi][ni][0], acc[mi][ni][1]);
            *(__nv_bfloat162*)&g_catb[base1] = __floats2bfloat162_rn(acc[mi][ni][2], acc[mi][ni][3]);
        }
    }
}

// ---------------- 4-stage pipelined bf16 tensor-core GEMMs ----------------
// BM=128, BN=128, BK=64; 256 threads = 8 warps (4M x 2N).
// MODE 0: h = relu(catb @ wb + conv_b)   -> g_hb (bf16), K=4096
// MODE 1: h1 = prelu(hb @ w1b + b1, pa)  -> g_h1 (fp32), K=512
template <int MODE>
__global__ void __launch_bounds__(256) mgemm_k(const float* __restrict__ bias,
                                               const float* __restrict__ pa) {
    constexpr int Kd = (MODE == 0) ? CDn : NH;
    constexpr int nk = Kd / 64;
    const __nv_bfloat16* A = (MODE == 0) ? g_catb : g_hb;
    const __nv_bfloat16* W = (MODE == 0) ? g_wb : g_w1b;
    extern __shared__ __nv_bfloat16 smem[];
    // layout: [As x4 stages][Bs x4 stages], stage = 8192 elems (16KB)
    int tid = threadIdx.x;
    int lane = tid & 31, warp = tid >> 5;
    int wm = (warp & 3) * 32, wn = (warp >> 2) * 64;
    int m0 = blockIdx.y * 128, n0 = blockIdx.x * 128;
    unsigned as_u = (unsigned)__cvta_generic_to_shared(smem);
    unsigned bs_u = as_u + 4 * 16384;

    int ar = tid >> 1, ac0 = (tid & 1) * 4;       // A: 128 rows x 8 chunks(16B)
    int br = tid >> 2, bc0 = (tid & 3) * 4;       // B: 64 rows x 16 chunks(16B)
    const __nv_bfloat16* Ag = A + (size_t)(m0 + ar) * Kd + ac0 * 8;
    const __nv_bfloat16* Wg = W + (size_t)br * NH + n0 + bc0 * 8;

    auto issue = [&](int it) {
        int s = it & 3;
        int k0 = it * 64;
        unsigned as_s = as_u + (unsigned)(s * 16384);
        unsigned bs_s = bs_u + (unsigned)(s * 16384);
        #pragma unroll
        for (int i = 0; i < 4; i++) {
            int c = ac0 + i;
            cpasync16(as_s + (unsigned)((ar * 64 + ((c ^ (ar & 7)) * 8)) * 2),
                      Ag + k0 + i * 8);
        }
        #pragma unroll
        for (int i = 0; i < 4; i++) {
            int c = bc0 + i;
            int cs = (c & 8) | ((c & 7) ^ (br & 7));
            cpasync16(bs_s + (unsigned)((br * 128 + cs * 8) * 2),
                      Wg + (size_t)k0 * NH + i * 8);
        }
        cpcommit();
    };

    float acc[2][8][4] = {};
    issue(0); issue(1); issue(2);
    for (int it = 0; it < nk; it++) {
        int s = it & 3;
        asm volatile("cp.async.wait_group 2;");
        __syncthreads();
        if (it + 3 < nk) issue(it + 3);
        unsigned as_s = as_u + (unsigned)(s * 16384);
        unsigned bs_s = bs_u + (unsigned)(s * 16384);
        #pragma unroll
        for (int k16 = 0; k16 < 4; k16++) {
            unsigned afr[2][4], bfr[4][4];
            #pragma unroll
            for (int mi = 0; mi < 2; mi++) {
                int row = wm + mi * 16 + (lane & 15);
                int c = k16 * 2 + (lane >> 4);
                ldsm4(afr[mi], as_s + (row * 64 + ((c ^ (row & 7)) * 8)) * 2);
            }
            #pragma unroll
            for (int ni = 0; ni < 4; ni++) {
                int krow = k16 * 16 + (lane & 15);
                int c = (wn >> 3) + ni * 2 + (lane >> 4);
                int cs = (c & 8) | ((c & 7) ^ (krow & 7));
                ldsm4t(bfr[ni], bs_s + (krow * 128 + cs * 8) * 2);
            }
            #pragma unroll
            for (int mi = 0; mi < 2; mi++)
                #pragma unroll
                for (int ni = 0; ni < 4; ni++) {
                    mma16816(acc[mi][ni * 2],     afr[mi], bfr[ni][0], bfr[ni][1]);
                    mma16816(acc[mi][ni * 2 + 1], afr[mi], bfr[ni][2], bfr[ni][3]);
                }
        }
    }

    // epilogue
    int rr = lane >> 2, cc = (lane & 3) * 2;
    #pragma unroll
    for (int mi = 0; mi < 2; mi++) {
        int gm = m0 + wm + mi * 16 + rr;
        #pragma unroll
        for (int ni = 0; ni < 8; ni++) {
            int gn = n0 + wn + ni * 8 + cc;
            float b0 = bias[gn], b1 = bias[gn + 1];
            float v0 = acc[mi][ni][0] + b0;
            float v1 = acc[mi][ni][1] + b1;
            float v2 = acc[mi][ni][2] + b0;
            float v3 = acc[mi][ni][3] + b1;
            if (MODE == 0) {
                v0 = fmaxf(v0, 0.f); v1 = fmaxf(v1, 0.f);
                v2 = fmaxf(v2, 0.f); v3 = fmaxf(v3, 0.f);
                *(__nv_bfloat162*)&g_hb[(size_t)gm * NH + gn]       = __floats2bfloat162_rn(v0, v1);
                *(__nv_bfloat162*)&g_hb[(size_t)(gm + 8) * NH + gn] = __floats2bfloat162_rn(v2, v3);
            } else {
                float p0 = pa[gn], p1 = pa[gn + 1];
                v0 = (v0 > 0.f) ? v0 : p0 * v0;
                v1 = (v1 > 0.f) ? v1 : p1 * v1;
                v2 = (v2 > 0.f) ? v2 : p0 * v2;
                v3 = (v3 > 0.f) ? v3 : p1 * v3;
                g_h1[(size_t)gm * NH + gn]           = v0;
                g_h1[(size_t)gm * NH + gn + 1]       = v1;
                g_h1[(size_t)(gm + 8) * NH + gn]     = v2;
                g_h1[(size_t)(gm + 8) * NH + gn + 1] = v3;
            }
        }
    }
}

// logits = h1 @ w2 + b2 ; softmax over 2
__global__ void fc2_softmax_k(const float* __restrict__ w2,
                              const float* __restrict__ b2,
                              float* __restrict__ out) {
    int gw = (blockIdx.x * blockDim.x + threadIdx.x) >> 5;
    int lane = threadIdx.x & 31;
    int nw = (gridDim.x * blockDim.x) >> 5;
    for (int r = gw; r < RWS; r += nw) {
        const float* h = g_h1 + (size_t)r * NH;
        float s0 = 0.f, s1 = 0.f;
        #pragma unroll
        for (int i = lane; i < NH; i += 32) {
            float v = h[i];
            s0 += v * w2[2 * i];
            s1 += v * w2[2 * i + 1];
        }
        #pragma unroll
        for (int o = 16; o; o >>= 1) {
            s0 += __shfl_xor_sync(0xffffffffu, s0, o);
            s1 += __shfl_xor_sync(0xffffffffu, s1, o);
        }
        if (lane == 0) {
            float l0 = s0 + b2[0], l1 = s1 + b2[1];
            float m = fmaxf(l0, l1);
            float e0 = expf(l0 - m), e1 = expf(l1 - m);
            float inv = 1.f / (e0 + e1);
            out[2 * r] = e0 * inv;
            out[2 * r + 1] = e1 * inv;
        }
    }
}

// ---------------- launch ----------------
extern "C" void kernel_launch(void* const* d_in, const int* in_sizes, int n_in,
                              void* d_out, int out_size) {
    const int*   indexes  = (const int*)d_in[0];
    const float* features = (const float*)d_in[1];
    const int*   labels   = (const int*)d_in[2];
    const int*   nbr      = (const int*)d_in[3];
    const float* conv_w   = (const float*)d_in[4];
    const float* conv_b   = (const float*)d_in[5];
    const float* w1       = (const float*)d_in[6];
    const float* b1       = (const float*)d_in[7];
    const float* pa       = (const float*)d_in[8];
    const float* w2       = (const float*)d_in[9];
    const float* b2       = (const float*)d_in[10];
    float* out = (float*)d_out;

    const int MGEMM_SMEM = 8 * 16384;   // 128 KB dynamic (4 stages x (As+Bs))
    cudaFuncSetAttribute(mgemm_k<0>, cudaFuncAttributeMaxDynamicSharedMemorySize, MGEMM_SMEM);
    cudaFuncSetAttribute(mgemm_k<1>, cudaFuncAttributeMaxDynamicSharedMemorySize, MGEMM_SMEM);

    convw_k<<<(CDn * NH + 255) / 256, 256>>>(conv_w, w1);
    zero_counts_k<<<NCn / 256, 256>>>();
    count_k<<<Np / 256, 256>>>(labels);
    scan_k<<<1, 1024>>>();
    scatter_k<<<Np / 256, 256>>>(labels);
    sortbucket_k<<<(NCn + 255) / 256, 256>>>();
    clumean_k<<<dim3(Dn / 256, NCn), 256>>>(features);
    build_cf_norm_k<<<RWS, 256>>>(indexes, features, labels, nbr);
    absplit_k<<<Bn, 256>>>();
    mask_k<<<Bn, 64>>>(labels, nbr);
    center_k<<<RWS, 256>>>();
    bagg_k<<<dim3(Dn / 128, Bn), 128>>>();
    mgemm_k<0><<<dim3(NH / 128, RWS / 128), 256, MGEMM_SMEM>>>(conv_b, nullptr);
    mgemm_k<1><<<dim3(NH / 128, RWS / 128), 256, MGEMM_SMEM>>>(b1, pa);
    fc2_softmax_k<<<64, 256>>>(w2, b2, out);
}